// round 3
// baseline (speedup 1.0000x reference)
#include <cuda_runtime.h>

#define NB 8
#define NS 1024
#define ND 1024
#define NH 16
#define NHD 64

// 32 MB each — static device scratch (no runtime allocation).
static __device__ float g_q[(size_t)NB * NH * NS * NHD];
static __device__ float g_k[(size_t)NB * NH * NS * NHD];
static __device__ float g_v[(size_t)NB * NH * NS * NHD];

// ---------------------------------------------------------------------------
// QKV projection: Y = X @ W, output scattered to [b, h, s, hd] layout.
// 128x128 output tile, BK=16, 256 threads, 8x8 register microtile.
// gridDim.z in {0,1,2} selects (Wq->g_q, Wk->g_k, Wv->g_v).
// ---------------------------------------------------------------------------
__global__ __launch_bounds__(256, 2)
void qkv_gemm(const float* __restrict__ X, const float* __restrict__ Wq,
              const float* __restrict__ Wk, const float* __restrict__ Wv) {
    __shared__ __align__(16) float As[16][128];  // A tile, transposed [k][m]
    __shared__ __align__(16) float Bs[16][128];  // B tile, natural    [k][n]

    const float* W;
    float* dst;
    if (blockIdx.z == 0)      { W = Wq; dst = g_q; }
    else if (blockIdx.z == 1) { W = Wk; dst = g_k; }
    else                      { W = Wv; dst = g_v; }

    const int m0 = blockIdx.y * 128;
    const int n0 = blockIdx.x * 128;
    const int tid = threadIdx.x;
    const int ty = tid >> 4;        // 0..15 -> 8 output rows each
    const int tx = tid & 15;        // 0..15 -> 8 output cols each

    const int am = tid >> 2;        // 0..63  (A tile row, +64 second half)
    const int ak = (tid & 3) << 2;  // 0,4,8,12
    const int bk = tid >> 5;        // 0..7   (B tile row, +8 second half)
    const int bn = (tid & 31) << 2; // 0..124

    float acc[8][8];
#pragma unroll
    for (int i = 0; i < 8; ++i)
#pragma unroll
        for (int j = 0; j < 8; ++j) acc[i][j] = 0.0f;

    for (int k0 = 0; k0 < ND; k0 += 16) {
        float4 a0 = *(const float4*)(X + (size_t)(m0 + am) * ND + k0 + ak);
        float4 a1 = *(const float4*)(X + (size_t)(m0 + am + 64) * ND + k0 + ak);
        float4 b0 = *(const float4*)(W + (size_t)(k0 + bk) * ND + n0 + bn);
        float4 b1 = *(const float4*)(W + (size_t)(k0 + bk + 8) * ND + n0 + bn);
        __syncthreads();
        As[ak + 0][am] = a0.x; As[ak + 1][am] = a0.y;
        As[ak + 2][am] = a0.z; As[ak + 3][am] = a0.w;
        As[ak + 0][am + 64] = a1.x; As[ak + 1][am + 64] = a1.y;
        As[ak + 2][am + 64] = a1.z; As[ak + 3][am + 64] = a1.w;
        *(float4*)&Bs[bk][bn]     = b0;
        *(float4*)&Bs[bk + 8][bn] = b1;
        __syncthreads();
#pragma unroll
        for (int kk = 0; kk < 16; ++kk) {
            float4 av0 = *(const float4*)&As[kk][ty * 8];
            float4 av1 = *(const float4*)&As[kk][ty * 8 + 4];
            float4 bv0 = *(const float4*)&Bs[kk][tx * 8];
            float4 bv1 = *(const float4*)&Bs[kk][tx * 8 + 4];
            float aa[8] = {av0.x, av0.y, av0.z, av0.w, av1.x, av1.y, av1.z, av1.w};
            float bb[8] = {bv0.x, bv0.y, bv0.z, bv0.w, bv1.x, bv1.y, bv1.z, bv1.w};
#pragma unroll
            for (int i = 0; i < 8; ++i)
#pragma unroll
                for (int j = 0; j < 8; ++j)
                    acc[i][j] = fmaf(aa[i], bb[j], acc[i][j]);
        }
    }

    // Epilogue: scatter to [b, h, s, hd]. Each thread's 8 cols live in one head.
#pragma unroll
    for (int i = 0; i < 8; ++i) {
        const int m  = m0 + ty * 8 + i;
        const int bi = m >> 10;
        const int s  = m & (NS - 1);
        const int n  = n0 + tx * 8;
        const int h  = n >> 6;
        const int hd = n & (NHD - 1);
        float* o = dst + ((((size_t)bi * NH + h) * NS + s) * NHD + hd);
        *(float4*)(o)     = make_float4(acc[i][0], acc[i][1], acc[i][2], acc[i][3]);
        *(float4*)(o + 4) = make_float4(acc[i][4], acc[i][5], acc[i][6], acc[i][7]);
    }
}

// ---------------------------------------------------------------------------
// Fused attention: one block per (b, h, 64-query tile). Streams 64-key tiles:
//   S = Q K^T / 8  ->  P = exp(S) * mask  ->  O += P V, rowsum += P
// Final: out = O / (rowsum + 1e-8), written to [b, s, h*64+hd].
// 128 threads; microtiles 4(q) x 8(cols). 48 KB static smem.
// ---------------------------------------------------------------------------
__global__ __launch_bounds__(128, 4)
void attn_fused(const float* __restrict__ mask, float* __restrict__ out) {
    __shared__ __align__(16) float Qs[64 * 64];   // [d][q] (transposed)
    __shared__ __align__(16) float KVs[64 * 64];  // phase 1: K [d][t]; phase 2: V [t][d]
    __shared__ __align__(16) float Pt[64 * 64];   // [t][q] (transposed P)

    const int qt  = blockIdx.x;   // query tile 0..15
    const int h   = blockIdx.y;
    const int b   = blockIdx.z;
    const int tid = threadIdx.x;
    const int ty  = tid >> 3;     // 0..15 -> 4 query rows each
    const int tx  = tid & 7;      // 0..7  -> 8 cols each

    const size_t bh = (size_t)b * NH + h;
    const float* qp   = g_q + (bh * NS + (size_t)qt * 64) * NHD;
    const float* kb   = g_k + bh * NS * NHD;
    const float* vb   = g_v + bh * NS * NHD;
    const float* mrow = mask + ((size_t)b * NS + (size_t)qt * 64) * NS;

    // Load Q tile transposed into smem (once per block).
    for (int it = tid; it < 1024; it += 128) {
        const int q = it >> 4;
        const int d = (it & 15) << 2;
        float4 v = *(const float4*)(qp + (size_t)q * NHD + d);
        Qs[(d + 0) * 64 + q] = v.x;
        Qs[(d + 1) * 64 + q] = v.y;
        Qs[(d + 2) * 64 + q] = v.z;
        Qs[(d + 3) * 64 + q] = v.w;
    }

    float acc[4][8];
#pragma unroll
    for (int i = 0; i < 4; ++i)
#pragma unroll
        for (int j = 0; j < 8; ++j) acc[i][j] = 0.0f;
    float rs[4] = {0.0f, 0.0f, 0.0f, 0.0f};

    for (int kt = 0; kt < 16; ++kt) {
        const float* kp = kb + (size_t)kt * 64 * NHD;
        __syncthreads();  // prior-iteration Ps/V reads complete
        // K tile transposed into smem. Lane-varying t => conflict-free stores
        // (costs strided global reads; K tiles are small and L2-resident).
        for (int it = tid; it < 1024; it += 128) {
            const int t = it & 63;
            const int d = (it >> 6) << 2;
            float4 v = *(const float4*)(kp + (size_t)t * NHD + d);
            KVs[(d + 0) * 64 + t] = v.x;
            KVs[(d + 1) * 64 + t] = v.y;
            KVs[(d + 2) * 64 + t] = v.z;
            KVs[(d + 3) * 64 + t] = v.w;
        }
        __syncthreads();

        // S = Q K^T  (contraction over d)
        float sacc[4][8];
#pragma unroll
        for (int i = 0; i < 4; ++i)
#pragma unroll
            for (int j = 0; j < 8; ++j) sacc[i][j] = 0.0f;

#pragma unroll 8
        for (int d = 0; d < 64; ++d) {
            float aa[4];
#pragma unroll
            for (int i = 0; i < 4; ++i) aa[i] = Qs[d * 64 + ty * 4 + i];
            float4 bv0 = *(const float4*)&KVs[d * 64 + tx * 8];
            float4 bv1 = *(const float4*)&KVs[d * 64 + tx * 8 + 4];
            float bb[8] = {bv0.x, bv0.y, bv0.z, bv0.w, bv1.x, bv1.y, bv1.z, bv1.w};
#pragma unroll
            for (int i = 0; i < 4; ++i)
#pragma unroll
                for (int j = 0; j < 8; ++j)
                    sacc[i][j] = fmaf(aa[i], bb[j], sacc[i][j]);
        }
        __syncthreads();  // K reads done; KVs free for V

        // Load V tile (natural [t][d], coalesced).
        const float* vp = vb + (size_t)kt * 64 * NHD;
        for (int it = tid; it < 1024; it += 128) {
            const int t = it >> 4;
            const int d = (it & 15) << 2;
            *(float4*)&KVs[t * 64 + d] = *(const float4*)(vp + (size_t)t * NHD + d);
        }

        // P = exp(S/8) * mask  -> Pt (transposed), accumulate row sums.
#pragma unroll
        for (int i = 0; i < 4; ++i) {
            const int q = ty * 4 + i;
            const float* mp = mrow + (size_t)q * NS + kt * 64 + tx * 8;
            float4 m0 = *(const float4*)(mp);
            float4 m1 = *(const float4*)(mp + 4);
            float mm[8] = {m0.x, m0.y, m0.z, m0.w, m1.x, m1.y, m1.z, m1.w};
            float p[8];
#pragma unroll
            for (int j = 0; j < 8; ++j)
                p[j] = __expf(sacc[i][j] * 0.125f) * mm[j];
            rs[i] += ((p[0] + p[1]) + (p[2] + p[3])) + ((p[4] + p[5]) + (p[6] + p[7]));
#pragma unroll
            for (int j = 0; j < 8; ++j)
                Pt[(tx * 8 + j) * 64 + q] = p[j];
        }
        __syncthreads();  // Pt + V visible

        // O += P V  (contraction over t)
#pragma unroll 8
        for (int t = 0; t < 64; ++t) {
            float aa[4];
#pragma unroll
            for (int i = 0; i < 4; ++i) aa[i] = Pt[t * 64 + ty * 4 + i];
            float4 bv0 = *(const float4*)&KVs[t * 64 + tx * 8];
            float4 bv1 = *(const float4*)&KVs[t * 64 + tx * 8 + 4];
            float bb[8] = {bv0.x, bv0.y, bv0.z, bv0.w, bv1.x, bv1.y, bv1.z, bv1.w};
#pragma unroll
            for (int i = 0; i < 4; ++i)
#pragma unroll
                for (int j = 0; j < 8; ++j)
                    acc[i][j] = fmaf(aa[i], bb[j], acc[i][j]);
        }
    }
    __syncthreads();  // last PV reads done; Pt reusable as reduction scratch

    // Reduce row sums across the 8 tx column-groups.
#pragma unroll
    for (int i = 0; i < 4; ++i)
        Pt[(ty * 4 + i) * 8 + tx] = rs[i];
    __syncthreads();

#pragma unroll
    for (int i = 0; i < 4; ++i) {
        const int q = ty * 4 + i;
        float tot = 0.0f;
#pragma unroll
        for (int x = 0; x < 8; ++x) tot += Pt[q * 8 + x];
        const float inv = 1.0f / (tot + 1e-8f);
        const int s = qt * 64 + q;
        float* op = out + ((size_t)b * NS + s) * ND + h * NHD + tx * 8;
        *(float4*)(op)     = make_float4(acc[i][0] * inv, acc[i][1] * inv,
                                         acc[i][2] * inv, acc[i][3] * inv);
        *(float4*)(op + 4) = make_float4(acc[i][4] * inv, acc[i][5] * inv,
                                         acc[i][6] * inv, acc[i][7] * inv);
    }
}

// ---------------------------------------------------------------------------
extern "C" void kernel_launch(void* const* d_in, const int* in_sizes, int n_in,
                              void* d_out, int out_size) {
    (void)in_sizes; (void)n_in; (void)out_size;
    const float* x    = (const float*)d_in[0];
    const float* mask = (const float*)d_in[1];
    const float* Wq   = (const float*)d_in[2];
    const float* Wk   = (const float*)d_in[3];
    const float* Wv   = (const float*)d_in[4];
    float* out = (float*)d_out;

    // Q/K/V projection: grid (N/128, M/128, 3)
    qkv_gemm<<<dim3(ND / 128, (NB * NS) / 128, 3), 256>>>(x, Wq, Wk, Wv);
    // Fused attention: grid (S/64, H, B)
    attn_fused<<<dim3(NS / 64, NH, NB), 128>>>(mask, out);
}